// round 17
// baseline (speedup 1.0000x reference)
#include <cuda_runtime.h>
#include <cstdint>

// Moment feature expansion, order 4, latent dim 16.
// out[b,t,:] = [1, x(16), f2(136), f3(816), f4(3876)] -> 4845 channels.
// Round 17: R16 + row-interleaved operand records. Both rows share every
// (k,j), so z3[k] = {f3A[k],f3A[k+1],f3B[k],f3B[k+1]} (16B/record) and
// zx[j] = {xA[j],xA[j+1],xB[j],xB[j+1]} let ONE LDS.128 each serve a pair
// for BOTH rows: f4 LDS instruction count halves (4 -> 2 per pair).

#define D    16
#define N2   136
#define N3   816
#define N4   3876
#define NOUT 4845
#define NTHREADS 256

#define F2S 137      // floats per f2 copy; copy1 base 548 B == 4 (mod 8)
#define XS  17       // floats per x  copy; copy1 base 68 B == 4 (mod 8)
#define MAXG 969     // max float4 groups in f4 (phase 0)

struct Tab2 { uint16_t v[N2]; };
struct Tab4 { uint16_t v[N4]; };
struct Tp3  { uint32_t v[2][408]; };        // [row-parity phase][pair]
struct Grp4 { uint32_t v[4][MAXG * 2]; };   // [gmem phase][group*2 + pair]

constexpr Tab2 gen2() {
    Tab2 t{}; int m = 0;
    for (int k = 0; k < D; k++)
        for (int j = 0; j <= k; j++)
            t.v[m++] = (uint16_t)((k << 4) | j);
    return t;
}

constexpr Tab4 gen4() {
    Tab4 t{}; int m = 0;
    int off[D] = {};
    for (int j = 0; j < D; j++) {
        int a = D + 2 - j;                       // 18 - j
        off[j] = N3 - a * (a - 1) * (a - 2) / 6;
    }
    for (int k = 0; k < N3; k++)
        for (int j = 0; j < D; j++)
            if (k >= off[j]) t.v[m++] = (uint16_t)((k << 4) | j);
    return t;
}

// Order-3 pair word: [10:0]=f2 byte off (incl parity copy), [11]=reset flag,
// [31:24]=x byte off (incl parity copy). (f2 stays parity-replicated.)
constexpr Tp3 genP3() {
    Tp3 t{};
    int off[D] = {};
    for (int j = 0; j < D; j++)
        off[j] = N2 - (D - j) * (D - j + 1) / 2;
    uint16_t kk[N3] = {}, jj[N3] = {};
    int m = 0;
    for (int k = 0; k < N2; k++)
        for (int j = 0; j < D; j++)
            if (k >= off[j]) { kk[m] = (uint16_t)k; jj[m] = (uint16_t)j; m++; }
    for (int h = 0; h < 2; h++) {
        int np = (N3 - h) / 2;                   // 408 or 407
        for (int p = 0; p < np; p++) {
            int a = h + 2 * p, b = a + 1;
            uint32_t k2 = kk[a], j = jj[a];
            uint32_t o2 = (k2 & 1u) * (F2S * 4u) + 4u * k2;
            uint32_t ox = (j & 1u) * (XS * 4u) + 4u * j;
            uint32_t fl = (kk[b] != k2) ? 1u : 0u;   // reset <=> !(j->j+1)
            t.v[h][p] = o2 | (fl << 11) | (ox << 24);
        }
    }
    return t;
}

// Order-4 pair word: [13:0]=z3 byte off (16*k), [14]=reset flag,
// [31:24]=zx byte off (16*j).
constexpr Grp4 genG() {
    Grp4 t{};
    int off[D] = {};
    for (int j = 0; j < D; j++) {
        int a = D + 2 - j;
        off[j] = N3 - a * (a - 1) * (a - 2) / 6;
    }
    uint16_t kk[N4] = {}, jj[N4] = {};
    int m = 0;
    for (int k = 0; k < N3; k++)
        for (int j = 0; j < D; j++)
            if (k >= off[j]) { kk[m] = (uint16_t)k; jj[m] = (uint16_t)j; m++; }
    for (int h = 0; h < 4; h++) {
        int nv = (N4 - h) >> 2;
        for (int g = 0; g < nv; g++)
            for (int pr = 0; pr < 2; pr++) {
                int a = h + 4 * g + 2 * pr, b = a + 1;
                uint32_t ka = kk[a], ja = jj[a];
                uint32_t fl = (kk[b] != ka) ? 1u : 0u;
                t.v[h][2 * g + pr] =
                    (16u * ka) | (fl << 14) | ((16u * ja) << 24);
            }
    }
    return t;
}

__device__ constexpr Tab2 c_t2 = gen2();
__device__ constexpr Tab4 c_t4 = gen4();
__device__ __align__(8)  constexpr Tp3  c_p3 = genP3();
__device__ __align__(16) constexpr Grp4 c_g4 = genG();

// One f4 pair for BOTH rows from interleaved records.
// rec f = {f3A[k], f3A[k+1], f3B[k], f3B[k+1]}, xv = {xA[j],xA[j+1],xB[j],xB[j+1]}
__device__ __forceinline__ void pair2(uint32_t u,
                                      const char* __restrict__ z3b,
                                      const char* __restrict__ zxb,
                                      float x0A, float x0B,
                                      float2& rA, float2& rB) {
    const float4 f  = *(const float4*)(z3b + (u & 0x3FFFu));
    const float4 xv = *(const float4*)(zxb + (u >> 24));
    rA.x = f.x * xv.x;
    rB.x = f.z * xv.z;
    const bool rst = (u & (1u << 14)) != 0;
    rA.y = rst ? f.y * x0A : f.x * xv.y;
    rB.y = rst ? f.w * x0B : f.z * xv.w;
}

__global__ __launch_bounds__(NTHREADS)
void Moment_2774548873409_kernel(const float* __restrict__ in,
                                 float* __restrict__ out,
                                 int half) {
    __shared__ __align__(16) float z3[4 * N3];      // interleaved f3 records
    __shared__ __align__(16) float zx[4 * 16];      // interleaved x records
    __shared__ __align__(16) float f2r[2][2 * F2S]; // f2 parity replicas
    __shared__ __align__(16) float xr[2][2 * XS];   // x parity replicas (o3)

    const int t = threadIdx.x;
    const int rowA = blockIdx.x;
    const int rowB = rowA + half;       // half % 4 == 0 -> same phases

    const size_t gA = (size_t)rowA * NOUT;
    const size_t gB = (size_t)rowB * NOUT;
    float* __restrict__ oA = out + gA;
    float* __restrict__ oB = out + gB;

    // --- orders 0, 1 (+ pad init), both rows ---
    if (t < D) {
        const float vA = in[(size_t)rowA * D + t];
        xr[0][t] = vA; xr[0][XS + t] = vA; oA[1 + t] = vA;
        const float vB = in[(size_t)rowB * D + t];
        xr[1][t] = vB; xr[1][XS + t] = vB; oB[1 + t] = vB;
    }
    if (t == 0) {
        oA[0] = 1.0f; oB[0] = 1.0f;
        #pragma unroll
        for (int r = 0; r < 2; r++) {
            xr[r][D] = 0.0f;   xr[r][XS + D] = 0.0f;
            f2r[r][N2] = 0.0f; f2r[r][F2S + N2] = 0.0f;
        }
        z3[4 * 815 + 1] = 0.0f; z3[4 * 815 + 3] = 0.0f;  // unread halves
    }
    __syncthreads();
    const float x0A = xr[0][0];
    const float x0B = xr[1][0];

    // --- order 2, both rows (272 items) + zx record fill (16 items) ---
    #pragma unroll
    for (int it = t; it < 2 * N2; it += NTHREADS) {
        const int r = (it >= N2) ? 1 : 0;
        const int i = it - r * N2;
        const uint16_t p = c_t2.v[i];
        const float v = xr[r][p >> 4] * xr[r][p & 15];
        f2r[r][i] = v; f2r[r][F2S + i] = v;
        (r ? oB : oA)[17 + i] = v;
    }
    if (t < 16) {   // zx[j] = {xA[j], xA[j+1], xB[j], xB[j+1]}; xr pad at [D]=0
        *(float4*)(zx + 4 * t) =
            make_float4(xr[0][t], xr[0][t + 1], xr[1][t], xr[1][t + 1]);
    }
    __syncthreads();

    const char* __restrict__ f2bA = (const char*)&f2r[0][0];
    const char* __restrict__ f2bB = (const char*)&f2r[1][0];
    const char* __restrict__ xbA  = (const char*)&xr[0][0];
    const char* __restrict__ xbB  = (const char*)&xr[1][0];

    // --- order 3: decode once, apply to both rows; write z3 records --------
    const int h3 = (int)((gA + 153) & 1);
    if (h3 == 0) {
        if (t < 408) {
            uint32_t w = c_p3.v[0][t];
            #pragma unroll 1
            for (int p = t; p < 408; p += NTHREADS) {
                const int pn = p + NTHREADS;
                const uint32_t wn = (pn < 408) ? c_p3.v[0][pn] : w;
                const uint32_t o2 = w & 0x7FFu;
                const uint32_t ox = w >> 24;
                const uint32_t fl = w & (1u << 11);
                const int m = 2 * p;
                const float2 fA  = *(const float2*)(f2bA + o2);
                const float2 xvA = *(const float2*)(xbA + ox);
                const float e0A = fA.x * xvA.x;
                const float e1A = fl ? fA.y * x0A : fA.x * xvA.y;
                const float2 fB  = *(const float2*)(f2bB + o2);
                const float2 xvB = *(const float2*)(xbB + ox);
                const float e0B = fB.x * xvB.x;
                const float e1B = fl ? fB.y * x0B : fB.x * xvB.y;
                // full record m (even)
                *(float4*)(z3 + 4 * m) = make_float4(e0A, e1A, e0B, e1B);
                // neighbors
                if (m > 0) { z3[4 * (m - 1) + 1] = e0A; z3[4 * (m - 1) + 3] = e0B; }
                z3[4 * (m + 1)] = e1A; z3[4 * (m + 1) + 2] = e1B;
                __stcs((float2*)(oA + 153 + m), make_float2(e0A, e1A));
                __stcs((float2*)(oB + 153 + m), make_float2(e0B, e1B));
                w = wn;
            }
        }
    } else {
        if (t < 407) {
            uint32_t w = c_p3.v[1][t];
            #pragma unroll 1
            for (int p = t; p < 407; p += NTHREADS) {
                const int pn = p + NTHREADS;
                const uint32_t wn = (pn < 407) ? c_p3.v[1][pn] : w;
                const uint32_t o2 = w & 0x7FFu;
                const uint32_t ox = w >> 24;
                const uint32_t fl = w & (1u << 11);
                const int m = 1 + 2 * p;
                const float2 fA  = *(const float2*)(f2bA + o2);
                const float2 xvA = *(const float2*)(xbA + ox);
                const float e0A = fA.x * xvA.x;
                const float e1A = fl ? fA.y * x0A : fA.x * xvA.y;
                const float2 fB  = *(const float2*)(f2bB + o2);
                const float2 xvB = *(const float2*)(xbB + ox);
                const float e0B = fB.x * xvB.x;
                const float e1B = fl ? fB.y * x0B : fB.x * xvB.y;
                // full record m (odd)
                *(float4*)(z3 + 4 * m) = make_float4(e0A, e1A, e0B, e1B);
                z3[4 * (m - 1) + 1] = e0A; z3[4 * (m - 1) + 3] = e0B;
                z3[4 * (m + 1)] = e1A; z3[4 * (m + 1) + 2] = e1B;
                __stcs((float2*)(oA + 153 + m), make_float2(e0A, e1A));
                __stcs((float2*)(oB + 153 + m), make_float2(e0B, e1B));
                w = wn;
            }
        }
        if (t == 0) {            // f3[0] = f2[0] * x0 -> record 0 .x/.z
            const float vA = f2r[0][0] * x0A;
            const float vB = f2r[1][0] * x0B;
            z3[0] = vA; z3[2] = vB;
            oA[153] = vA; oB[153] = vB;
        }
        if (t == 1) {            // f3[815] = f2[135] * x[15]
            const float vA = f2r[0][135] * xr[0][15];
            const float vB = f2r[1][135] * xr[1][15];
            z3[4 * 815] = vA; z3[4 * 815 + 2] = vB;
            z3[4 * 814 + 1] = vA; z3[4 * 814 + 3] = vB;
            oA[153 + 815] = vA; oB[153 + 815] = vB;
        }
    }
    __syncthreads();

    // --- order 4: interleaved records, 2 LDS.128 per pair for both rows ----
    const char* __restrict__ z3b = (const char*)z3;
    const char* __restrict__ zxb = (const char*)zx;
    float* __restrict__ o4A = oA + 969;
    float* __restrict__ o4B = oB + 969;
    const int a4 = (int)((gA + 969) & 3);
    const int h  = (4 - a4) & 3;

    const int nv = (N4 - h) >> 2;
    float4* __restrict__ ovA = (float4*)(o4A + h);
    float4* __restrict__ ovB = (float4*)(o4B + h);

    // 128B-aligned store windows (rowB shares the phase).
    const int c = (int)(((0u - (uint32_t)(uintptr_t)ovA) & 127u) >> 4); // 0..7

    const int headN = h + 4 * c;                 // scalar head, <= 31
    if (t < headN) {
        const uint16_t p = c_t4.v[t];
        const int k = p >> 4, j = p & 15;
        __stcs(o4A + t, z3[4 * k] * xr[0][j]);
        __stcs(o4B + t, z3[4 * k + 2] * xr[1][j]);
    }

    const uint2* __restrict__ gt = (const uint2*)&c_g4.v[h][0];
    const int g0 = c + t;
    if (g0 < nv) {
        uint2 w = gt[g0];                        // prefetch first iteration
        #pragma unroll 1
        for (int g = g0; g < nv; g += NTHREADS) {
            const int gn = g + NTHREADS;
            const uint2 wn = (gn < nv) ? gt[gn] : w;   // prefetch next
            float2 a0, b0, a1, b1;
            pair2(w.x, z3b, zxb, x0A, x0B, a0, b0);
            pair2(w.y, z3b, zxb, x0A, x0B, a1, b1);
            __stcs(ovA + g, make_float4(a0.x, a0.y, a1.x, a1.y));
            __stcs(ovB + g, make_float4(b0.x, b0.y, b1.x, b1.y));
            w = wn;
        }
    }

    const int done = h + 4 * nv;
    if (t < N4 - done) {
        const int m = done + t;
        const uint16_t p = c_t4.v[m];
        const int k = p >> 4, j = p & 15;
        __stcs(o4A + m, z3[4 * k] * xr[0][j]);
        __stcs(o4B + m, z3[4 * k + 2] * xr[1][j]);
    }
}

extern "C" void kernel_launch(void* const* d_in, const int* in_sizes, int n_in,
                              void* d_out, int out_size) {
    const float* in = (const float*)d_in[0];
    float* out = (float*)d_out;
    const int rows = in_sizes[0] / D;            // 8192
    const int half = rows >> 1;                  // 4096, % 4 == 0
    Moment_2774548873409_kernel<<<half, NTHREADS>>>(in, out, half);
}